// round 12
// baseline (speedup 1.0000x reference)
#include <cuda_runtime.h>
#include <cstdint>

// Global accumulators (zero-init at module load; last block resets each run).
__device__ double g_sum0;                  // class-0 picked log-prob sum
__device__ double g_sum1;                  // class-1 picked log-prob sum
__device__ unsigned long long g_cnt1;      // class-1 count
__device__ unsigned int g_blocks_done;     // retirement counter

#define TILE_PAIRS      256      // pairs per tile (512 tokens) -> 4 KB/stage
#define TILES_PER_BLOCK 16       // pairs per block = 4096 (grid stays 1024)
#define NSTAGE          7        // 28 KB smem; >=7 CTAs/SM -> still one wave

__device__ __forceinline__ void cp_async16(void* smem_dst, const void* gmem_src) {
    uint32_t s = (uint32_t)__cvta_generic_to_shared(smem_dst);
    asm volatile("cp.async.cg.shared.global [%0], [%1], 16;" :: "r"(s), "l"(gmem_src));
}
__device__ __forceinline__ void cp_async_commit() {
    asm volatile("cp.async.commit_group;" ::: "memory");
}
template <int N>
__device__ __forceinline__ void cp_async_wait() {
    asm volatile("cp.async.wait_group %0;" :: "n"(N) : "memory");
}

__device__ __forceinline__ void proc_pair(float4 a, int2 t,
                                          float& s0, float& s1, int& c1) {
    {
        float m   = fmaxf(a.x, a.y);
        float d   = -fabsf(a.x - a.y);
        float lse = m + __logf(1.0f + __expf(d));
        if (t.x != 0) { s1 += a.y - lse; c1 += 1; }
        else          { s0 += a.x - lse; }
    }
    {
        float m   = fmaxf(a.z, a.w);
        float d   = -fabsf(a.z - a.w);
        float lse = m + __logf(1.0f + __expf(d));
        if (t.y != 0) { s1 += a.w - lse; c1 += 1; }
        else          { s0 += a.z - lse; }
    }
}

// Barrier-free per-thread streaming pipeline (R8-R11): each thread cp.asyncs
// ONLY the smem words it alone reads; cp.async.wait_group gives self-
// visibility; no __syncthreads in the loop. This round: 7 stages (96B/thread
// in flight) + targets software-prefetched one tile ahead in registers so the
// LDG.64 latency is fully covered by a whole pipeline iteration.
__global__ __launch_bounds__(256) void nll_pipe_kernel(
    const float* __restrict__ x,
    const int* __restrict__ targets,
    long long n_tokens,
    float* __restrict__ out)
{
    __shared__ float4 xbuf[NSTAGE][TILE_PAIRS];   // 7 x 4 KB

    const int tix = threadIdx.x;
    const long long n_pairs = n_tokens >> 1;
    const long long P0 = (long long)blockIdx.x * (TILES_PER_BLOCK * TILE_PAIRS);

    const float4* x4 = reinterpret_cast<const float4*>(x);
    const int2*   t2 = reinterpret_cast<const int2*>(targets);

    float s0 = 0.0f, s1 = 0.0f;
    int   c1 = 0;

    const bool full_block = (P0 + TILES_PER_BLOCK * TILE_PAIRS) <= n_pairs;

    if (full_block) {
        // Prefetch first NSTAGE x-tiles (one commit group per tile).
        #pragma unroll
        for (int i = 0; i < NSTAGE; i++) {
            cp_async16(&xbuf[i][tix], x4 + P0 + i * TILE_PAIRS + tix);
            cp_async_commit();
        }

        // Target prefetch: tile 0's pair, issued long before use.
        int2 bnext = t2[P0 + tix];

        int st = 0;
        #pragma unroll
        for (int i = 0; i < TILES_PER_BLOCK; i++) {
            int2 b0 = bnext;
            // Issue next tile's target LDG a full iteration ahead.
            if (i + 1 < TILES_PER_BLOCK)
                bnext = t2[P0 + (long long)(i + 1) * TILE_PAIRS + tix];

            cp_async_wait<NSTAGE - 1>();   // this thread's tile-i copy done

            // Drain smem slot into registers (frees stage st for THIS thread;
            // no other thread ever touches this address).
            float4 a0 = xbuf[st][tix];

            // Refill stage st for tile i+NSTAGE before computing.
            if (i + NSTAGE < TILES_PER_BLOCK) {
                cp_async16(&xbuf[st][tix],
                           x4 + P0 + (long long)(i + NSTAGE) * TILE_PAIRS + tix);
            }
            cp_async_commit();   // keep group count in lockstep every iter

            proc_pair(a0, b0, s0, s1, c1);

            st = (st == NSTAGE - 1) ? 0 : st + 1;
        }
    } else {
        // Generic guarded path for the boundary block (rare / other shapes).
        for (long long p = P0 + tix; p < n_pairs &&
             p < P0 + TILES_PER_BLOCK * TILE_PAIRS; p += 256) {
            proc_pair(x4[p], t2[p], s0, s1, c1);
        }
    }

    // Odd trailing token.
    if ((n_tokens & 1) && blockIdx.x == 0 && tix == 0) {
        long long i = n_tokens - 1;
        float x0 = x[2 * i], x1v = x[2 * i + 1];
        int   t  = targets[i];
        float m   = fmaxf(x0, x1v);
        float d   = -fabsf(x0 - x1v);
        float lse = m + __logf(1.0f + __expf(d));
        if (t != 0) { s1 += x1v - lse; c1 += 1; }
        else        { s0 += x0 - lse; }
    }

    // warp reduction
    #pragma unroll
    for (int off = 16; off > 0; off >>= 1) {
        s0 += __shfl_down_sync(0xFFFFFFFFu, s0, off);
        s1 += __shfl_down_sync(0xFFFFFFFFu, s1, off);
        c1 += __shfl_down_sync(0xFFFFFFFFu, c1, off);
    }

    __shared__ float sh0[8];
    __shared__ float sh1[8];
    __shared__ int   shc[8];
    const int lane = tix & 31;
    const int wid  = tix >> 5;
    if (lane == 0) { sh0[wid] = s0; sh1[wid] = s1; shc[wid] = c1; }
    __syncthreads();

    __shared__ bool is_last;
    if (wid == 0) {
        s0 = (lane < 8) ? sh0[lane] : 0.0f;
        s1 = (lane < 8) ? sh1[lane] : 0.0f;
        c1 = (lane < 8) ? shc[lane] : 0;
        #pragma unroll
        for (int off = 4; off > 0; off >>= 1) {
            s0 += __shfl_down_sync(0xFFFFFFFFu, s0, off);
            s1 += __shfl_down_sync(0xFFFFFFFFu, s1, off);
            c1 += __shfl_down_sync(0xFFFFFFFFu, c1, off);
        }
        if (lane == 0) {
            atomicAdd(&g_sum0, (double)s0);
            atomicAdd(&g_sum1, (double)s1);
            atomicAdd(&g_cnt1, (unsigned long long)c1);
            __threadfence();
            unsigned int done = atomicAdd(&g_blocks_done, 1u);
            is_last = (done == gridDim.x - 1u);
        }
    }
    __syncthreads();

    if (is_last && tix == 0) {
        __threadfence();
        double sum0 = g_sum0;
        double sum1 = g_sum1;
        unsigned long long n1 = g_cnt1;
        unsigned long long n0 = (unsigned long long)n_tokens - n1;
        double r = (n1 > 0) ? (-sum1 / (double)n1) : 0.0;
        double p = (n0 > 0) ? (-sum0 / (double)n0) : 0.0;
        out[0] = (float)(p + r);
        g_sum0 = 0.0;
        g_sum1 = 0.0;
        g_cnt1 = 0ull;
        g_blocks_done = 0u;
    }
}

extern "C" void kernel_launch(void* const* d_in, const int* in_sizes, int n_in,
                              void* d_out, int out_size) {
    const float* x       = (const float*)d_in[0];
    const int*   targets = (const int*)d_in[1];
    float*       out     = (float*)d_out;

    const long long n_tokens = (long long)in_sizes[1];
    const long long n_pairs  = (n_tokens + 1) / 2;

    const int block = 256;
    const long long pairs_per_block = TILES_PER_BLOCK * TILE_PAIRS;  // 4096
    int grid = (int)((n_pairs + pairs_per_block - 1) / pairs_per_block);
    if (grid < 1) grid = 1;
    nll_pipe_kernel<<<grid, block>>>(x, targets, n_tokens, out);
}

// round 13
// speedup vs baseline: 1.0448x; 1.0448x over previous
#include <cuda_runtime.h>
#include <cstdint>

// Global accumulators (zero-init at module load; last block resets each run).
__device__ double g_sum0;                  // class-0 picked log-prob sum
__device__ double g_sum1;                  // class-1 picked log-prob sum
__device__ unsigned long long g_cnt1;      // class-1 count
__device__ unsigned int g_blocks_done;     // retirement counter

#define TILE_PAIRS      512      // pairs per tile (1024 tokens) -> 8 KB/stage
#define TILES_PER_BLOCK 8        // pairs per block = 4096 (grid = 1024)
#define NSTAGE          3        // 24 KB smem -> 8 CTAs/SM, single wave

__device__ __forceinline__ void cp_async16(void* smem_dst, const void* gmem_src) {
    uint32_t s = (uint32_t)__cvta_generic_to_shared(smem_dst);
    asm volatile("cp.async.cg.shared.global [%0], [%1], 16;" :: "r"(s), "l"(gmem_src));
}
__device__ __forceinline__ void cp_async_commit() {
    asm volatile("cp.async.commit_group;" ::: "memory");
}
template <int N>
__device__ __forceinline__ void cp_async_wait() {
    asm volatile("cp.async.wait_group %0;" :: "n"(N) : "memory");
}

__device__ __forceinline__ void proc_pair(float4 a, int2 t,
                                          float& s0, float& s1, int& c1) {
    {
        float m   = fmaxf(a.x, a.y);
        float d   = -fabsf(a.x - a.y);
        float lse = m + __logf(1.0f + __expf(d));
        if (t.x != 0) { s1 += a.y - lse; c1 += 1; }
        else          { s0 += a.x - lse; }
    }
    {
        float m   = fmaxf(a.z, a.w);
        float d   = -fabsf(a.z - a.w);
        float lse = m + __logf(1.0f + __expf(d));
        if (t.y != 0) { s1 += a.w - lse; c1 += 1; }
        else          { s0 += a.z - lse; }
    }
}

// Barrier-free per-thread streaming pipeline (best-measured R10 geometry):
// each thread cp.asyncs ONLY the smem words it alone reads, so
// cp.async.wait_group gives self-visibility; no __syncthreads in the loop.
// Added: targets register-prefetched one full tile ahead so the LDG.64 has an
// entire pipeline iteration to complete before use.
__global__ __launch_bounds__(256, 8) void nll_pipe_kernel(
    const float* __restrict__ x,
    const int* __restrict__ targets,
    long long n_tokens,
    float* __restrict__ out)
{
    __shared__ float4 xbuf[NSTAGE][TILE_PAIRS];   // 3 x 8 KB

    const int tix = threadIdx.x;
    const long long n_pairs = n_tokens >> 1;
    const long long P0 = (long long)blockIdx.x * (TILES_PER_BLOCK * TILE_PAIRS);

    const float4* x4 = reinterpret_cast<const float4*>(x);
    const int2*   t2 = reinterpret_cast<const int2*>(targets);

    float s0 = 0.0f, s1 = 0.0f;
    int   c1 = 0;

    const bool full_block = (P0 + TILES_PER_BLOCK * TILE_PAIRS) <= n_pairs;

    if (full_block) {
        // Prefetch first NSTAGE x-tiles (one commit group per tile).
        #pragma unroll
        for (int i = 0; i < NSTAGE; i++) {
            const float4* src = x4 + P0 + i * TILE_PAIRS + tix;
            cp_async16(&xbuf[i][tix],       src);
            cp_async16(&xbuf[i][256 + tix], src + 256);
            cp_async_commit();
        }

        // Target prefetch: tile 0's pairs, issued long before use.
        int2 pb0 = t2[P0 + tix];
        int2 pb1 = t2[P0 + 256 + tix];

        int st = 0;
        #pragma unroll
        for (int i = 0; i < TILES_PER_BLOCK; i++) {
            int2 b0 = pb0;
            int2 b1 = pb1;
            // Issue next tile's target LDGs a full iteration ahead.
            if (i + 1 < TILES_PER_BLOCK) {
                const int2* tp = t2 + P0 + (long long)(i + 1) * TILE_PAIRS + tix;
                pb0 = tp[0];
                pb1 = tp[256];
            }

            cp_async_wait<NSTAGE - 1>();   // this thread's tile-i copy done

            // Drain smem slots into registers (frees stage st for THIS
            // thread; no other thread ever touches these addresses).
            float4 a0 = xbuf[st][tix];
            float4 a1 = xbuf[st][256 + tix];

            // Refill stage st for tile i+NSTAGE before computing.
            if (i + NSTAGE < TILES_PER_BLOCK) {
                const float4* src = x4 + P0 + (long long)(i + NSTAGE) * TILE_PAIRS + tix;
                cp_async16(&xbuf[st][tix],       src);
                cp_async16(&xbuf[st][256 + tix], src + 256);
            }
            cp_async_commit();   // keep group count in lockstep every iter

            proc_pair(a0, b0, s0, s1, c1);
            proc_pair(a1, b1, s0, s1, c1);

            st = (st == NSTAGE - 1) ? 0 : st + 1;
        }
    } else {
        // Generic guarded path for the boundary block (rare / other shapes).
        for (long long p = P0 + tix; p < n_pairs &&
             p < P0 + TILES_PER_BLOCK * TILE_PAIRS; p += 256) {
            proc_pair(x4[p], t2[p], s0, s1, c1);
        }
    }

    // Odd trailing token.
    if ((n_tokens & 1) && blockIdx.x == 0 && tix == 0) {
        long long i = n_tokens - 1;
        float x0 = x[2 * i], x1v = x[2 * i + 1];
        int   t  = targets[i];
        float m   = fmaxf(x0, x1v);
        float d   = -fabsf(x0 - x1v);
        float lse = m + __logf(1.0f + __expf(d));
        if (t != 0) { s1 += x1v - lse; c1 += 1; }
        else        { s0 += x0 - lse; }
    }

    // warp reduction
    #pragma unroll
    for (int off = 16; off > 0; off >>= 1) {
        s0 += __shfl_down_sync(0xFFFFFFFFu, s0, off);
        s1 += __shfl_down_sync(0xFFFFFFFFu, s1, off);
        c1 += __shfl_down_sync(0xFFFFFFFFu, c1, off);
    }

    __shared__ float sh0[8];
    __shared__ float sh1[8];
    __shared__ int   shc[8];
    const int lane = tix & 31;
    const int wid  = tix >> 5;
    if (lane == 0) { sh0[wid] = s0; sh1[wid] = s1; shc[wid] = c1; }
    __syncthreads();

    __shared__ bool is_last;
    if (wid == 0) {
        s0 = (lane < 8) ? sh0[lane] : 0.0f;
        s1 = (lane < 8) ? sh1[lane] : 0.0f;
        c1 = (lane < 8) ? shc[lane] : 0;
        #pragma unroll
        for (int off = 4; off > 0; off >>= 1) {
            s0 += __shfl_down_sync(0xFFFFFFFFu, s0, off);
            s1 += __shfl_down_sync(0xFFFFFFFFu, s1, off);
            c1 += __shfl_down_sync(0xFFFFFFFFu, c1, off);
        }
        if (lane == 0) {
            atomicAdd(&g_sum0, (double)s0);
            atomicAdd(&g_sum1, (double)s1);
            atomicAdd(&g_cnt1, (unsigned long long)c1);
            __threadfence();
            unsigned int done = atomicAdd(&g_blocks_done, 1u);
            is_last = (done == gridDim.x - 1u);
        }
    }
    __syncthreads();

    if (is_last && tix == 0) {
        __threadfence();
        double sum0 = g_sum0;
        double sum1 = g_sum1;
        unsigned long long n1 = g_cnt1;
        unsigned long long n0 = (unsigned long long)n_tokens - n1;
        double r = (n1 > 0) ? (-sum1 / (double)n1) : 0.0;
        double p = (n0 > 0) ? (-sum0 / (double)n0) : 0.0;
        out[0] = (float)(p + r);
        g_sum0 = 0.0;
        g_sum1 = 0.0;
        g_cnt1 = 0ull;
        g_blocks_done = 0u;
    }
}

extern "C" void kernel_launch(void* const* d_in, const int* in_sizes, int n_in,
                              void* d_out, int out_size) {
    const float* x       = (const float*)d_in[0];
    const int*   targets = (const int*)d_in[1];
    float*       out     = (float*)d_out;

    const long long n_tokens = (long long)in_sizes[1];
    const long long n_pairs  = (n_tokens + 1) / 2;

    const int block = 256;
    const long long pairs_per_block = TILES_PER_BLOCK * TILE_PAIRS;  // 4096
    int grid = (int)((n_pairs + pairs_per_block - 1) / pairs_per_block);
    if (grid < 1) grid = 1;
    nll_pipe_kernel<<<grid, block>>>(x, targets, n_tokens, out);
}